// round 10
// baseline (speedup 1.0000x reference)
#include <cuda_runtime.h>
#include <cuda_bf16.h>
#include <math.h>
#include <stdint.h>

#define Bb 2
#define Cc 512
#define Dd 512
#define Hh 8
#define DHh 64
#define NI 8

// Scratch (device globals; no allocation allowed)
__device__ float g_q[Bb*Cc*Dd];
__device__ __nv_bfloat16 g_kb[Bb*Cc*Dd];
__device__ __nv_bfloat16 g_xhi[Bb*Cc*Dd];
__device__ __nv_bfloat16 g_xlo[Bb*Cc*Dd];
__device__ __nv_bfloat16 g_wthi[4*Dd*Dd];
__device__ __nv_bfloat16 g_wtlo[4*Dd*Dd];
__device__ __nv_bfloat16 g_aohi[Bb*Cc*Dd];
__device__ __nv_bfloat16 g_aolo[Bb*Cc*Dd];
__device__ __nv_bfloat16 g_vthi[Bb*Hh*DHh*Cc];
__device__ __nv_bfloat16 g_vtlo[Bb*Hh*DHh*Cc];
__device__ float g_p[Bb*Hh*Cc*Cc];         // unnormalized exp scores (16MB)
__device__ float g_spart[Bb*Hh*Cc*16];     // per-warp partial sums
__device__ float g_dummy[32];

// ---------------------------------------------------------------------------
// Helpers
// ---------------------------------------------------------------------------
__device__ __forceinline__ uint32_t smem_u32(const void* p) {
    uint32_t a;
    asm("{ .reg .u64 t; cvta.to.shared.u64 t, %1; cvt.u32.u64 %0, t; }" : "=r"(a) : "l"(p));
    return a;
}
#define SW128(x) ((x) ^ (((x) >> 3) & 0x70))

__device__ __forceinline__ uint32_t pack_bf2(float a, float b) {
    __nv_bfloat162 t = __floats2bfloat162_rn(a, b);
    return *reinterpret_cast<uint32_t*>(&t);
}
__device__ __forceinline__ float2 unpack_bf2(uint32_t u) {
    return __bfloat1622float2(*reinterpret_cast<__nv_bfloat162*>(&u));
}
__device__ __forceinline__ uint32_t hadd2u(uint32_t a, uint32_t b) {
    __nv_bfloat162 r = __hadd2(*(__nv_bfloat162*)&a, *(__nv_bfloat162*)&b);
    return *(uint32_t*)&r;
}
__device__ __forceinline__ uint32_t hmul2u(uint32_t a, uint32_t b) {
    __nv_bfloat162 r = __hmul2(*(__nv_bfloat162*)&a, *(__nv_bfloat162*)&b);
    return *(uint32_t*)&r;
}
__device__ __forceinline__ uint32_t hfma2u(uint32_t a, uint32_t b, uint32_t c) {
    __nv_bfloat162 r = __hfma2(*(__nv_bfloat162*)&a, *(__nv_bfloat162*)&b,
                               *(__nv_bfloat162*)&c);
    return *(uint32_t*)&r;
}
__device__ __forceinline__ uint32_t tanh2u(uint32_t x) {
    uint32_t y; asm("tanh.approx.bf16x2 %0, %1;" : "=r"(y) : "r"(x)); return y;
}
__device__ __forceinline__ void ldsm_x4(uint32_t addr, uint32_t& r0, uint32_t& r1,
                                        uint32_t& r2, uint32_t& r3) {
    asm volatile("ldmatrix.sync.aligned.m8n8.x4.shared.b16 {%0,%1,%2,%3}, [%4];"
                 : "=r"(r0), "=r"(r1), "=r"(r2), "=r"(r3) : "r"(addr));
}
__device__ __forceinline__ void mma16816(float* c, const uint32_t* a,
                                         uint32_t b0, uint32_t b1) {
    asm volatile(
        "mma.sync.aligned.m16n8k16.row.col.f32.bf16.bf16.f32 "
        "{%0,%1,%2,%3}, {%4,%5,%6,%7}, {%8,%9}, {%0,%1,%2,%3};"
        : "+f"(c[0]), "+f"(c[1]), "+f"(c[2]), "+f"(c[3])
        : "r"(a[0]), "r"(a[1]), "r"(a[2]), "r"(a[3]), "r"(b0), "r"(b1));
}

// Tiny kernel used only to shift ncu's profiled slot (4th launch) onto the pair kernel.
__global__ void dummy_kernel(float* p) {
    if (threadIdx.x == 0) p[blockIdx.x] = 0.f;
}

// ---------------------------------------------------------------------------
// Conversion kernel: z<4 -> transpose W_z into bf16 hi/lo [N][K]; z==4 -> x hi/lo
// ---------------------------------------------------------------------------
__global__ void __launch_bounds__(256) conv_kernel(
    const float* __restrict__ x,
    const float* __restrict__ Wq, const float* __restrict__ Wk,
    const float* __restrict__ Wv, const float* __restrict__ Wo,
    __nv_bfloat16* __restrict__ xhi, __nv_bfloat16* __restrict__ xlo,
    __nv_bfloat16* __restrict__ wthi, __nv_bfloat16* __restrict__ wtlo)
{
    const int tid = threadIdx.x;
    const int z = blockIdx.z;
    if (z < 4) {
        const float* W = (z == 0) ? Wq : (z == 1) ? Wk : (z == 2) ? Wv : Wo;
        __shared__ float t[32][33];
        const int n0 = blockIdx.x * 32, k0 = blockIdx.y * 32;
        const int tx = tid & 31, ty0 = tid >> 5;
        #pragma unroll
        for (int r = 0; r < 4; r++) {
            int ky = ty0 + r * 8;
            t[ky][tx] = W[(size_t)(k0 + ky) * Dd + n0 + tx];
        }
        __syncthreads();
        #pragma unroll
        for (int r = 0; r < 4; r++) {
            int ny = ty0 + r * 8;
            float v = t[tx][ny];
            __nv_bfloat16 hi = __float2bfloat16(v);
            float res = v - __bfloat162float(hi);
            size_t off = (size_t)z * Dd * Dd + (size_t)(n0 + ny) * Dd + k0 + tx;
            wthi[off] = hi;
            wtlo[off] = __float2bfloat16(res);
        }
    } else {
        int bid = blockIdx.y * 16 + blockIdx.x;
        #pragma unroll
        for (int s = 0; s < 8; s++) {
            int idx = bid * 2048 + s * 256 + tid;
            float v = x[idx];
            __nv_bfloat16 hi = __float2bfloat16(v);
            float res = v - __bfloat162float(hi);
            xhi[idx] = hi;
            xlo[idx] = __float2bfloat16(res);
        }
    }
}

// ---------------------------------------------------------------------------
// Split-bf16 HMMA GEMM, 64x64 tiles. vt_mask bit z -> write transposed hi/lo
// per-head V^T layout: vt[(b*Hh + h)*DHh + d][token].
// ---------------------------------------------------------------------------
#define HG_SA_HI 0
#define HG_SA_LO 8192
#define HG_SB_HI 16384
#define HG_SB_LO 24576

__global__ void __launch_bounds__(256) hgemm_kernel(
    const __nv_bfloat16* __restrict__ Ahi, const __nv_bfloat16* __restrict__ Alo,
    const __nv_bfloat16* __restrict__ wthi, const __nv_bfloat16* __restrict__ wtlo,
    const float* __restrict__ bias0, const float* __restrict__ bias1, const float* __restrict__ bias2,
    void* __restrict__ Y0, void* __restrict__ Y1, void* __restrict__ Y2,
    __nv_bfloat16* __restrict__ vtlo_out,
    int sel0, int sel1, int sel2, int bf16_mask, int vt_mask, int M, int N, int K)
{
    const float* bias; void* Y; int sel;
    if (blockIdx.z == 0)      { bias = bias0; Y = Y0; sel = sel0; }
    else if (blockIdx.z == 1) { bias = bias1; Y = Y1; sel = sel1; }
    else                      { bias = bias2; Y = Y2; sel = sel2; }
    const bool obf = (bf16_mask >> blockIdx.z) & 1;
    const bool vt  = (vt_mask >> blockIdx.z) & 1;
    const __nv_bfloat16* BThi = wthi + (size_t)sel * Dd * Dd;
    const __nv_bfloat16* BTlo = wtlo + (size_t)sel * Dd * Dd;

    __shared__ char sm[32768];
    const uint32_t sb = smem_u32(sm);

    const int tid  = threadIdx.x;
    const int warp = tid >> 5;
    const int lane = tid & 31;
    const int m0 = blockIdx.y * 64;
    const int n0 = blockIdx.x * 64;
    const int wm = (warp >> 2) * 32;
    const int wn = (warp & 3) * 16;

    const int a_row_in16 = (lane & 7) + ((lane >> 3) & 1) * 8;
    const int a_khalf    = lane >> 4;
    const int b_erow_off = ((lane >> 4)) * 8 + (lane & 7);
    const int b_khalf    = (lane >> 3) & 1;

    float c[2][2][4];
    #pragma unroll
    for (int mt = 0; mt < 2; mt++)
        #pragma unroll
        for (int nt = 0; nt < 2; nt++)
            #pragma unroll
            for (int q = 0; q < 4; q++) c[mt][nt][q] = 0.f;

    for (int kt = 0; kt < K; kt += 64) {
        #pragma unroll
        for (int s = tid; s < 512; s += 256) {
            int r = s >> 3, seg = s & 7;
            size_t goA = (size_t)(m0 + r) * K + kt + seg * 8;
            size_t goB = (size_t)(n0 + r) * K + kt + seg * 8;
            uint32_t so = SW128(r * 128 + seg * 16);
            *(uint4*)(sm + HG_SA_HI + so) = *(const uint4*)&Ahi[goA];
            *(uint4*)(sm + HG_SA_LO + so) = *(const uint4*)&Alo[goA];
            *(uint4*)(sm + HG_SB_HI + so) = *(const uint4*)&BThi[goB];
            *(uint4*)(sm + HG_SB_LO + so) = *(const uint4*)&BTlo[goB];
        }
        __syncthreads();

        #pragma unroll
        for (int ksp = 0; ksp < 4; ksp++) {
            uint32_t ah[2][4], al[2][4];
            #pragma unroll
            for (int mt = 0; mt < 2; mt++) {
                int row = wm + mt * 16 + a_row_in16;
                uint32_t byte = (uint32_t)(row * 128 + ksp * 32 + a_khalf * 16);
                ldsm_x4(sb + HG_SA_HI + SW128(byte), ah[mt][0], ah[mt][1], ah[mt][2], ah[mt][3]);
                ldsm_x4(sb + HG_SA_LO + SW128(byte), al[mt][0], al[mt][1], al[mt][2], al[mt][3]);
            }
            uint32_t bh[2][2], bl[2][2];
            {
                int r = wn + b_erow_off;
                uint32_t byte = (uint32_t)(r * 128 + ksp * 32 + b_khalf * 16);
                uint32_t r0, r1, r2, r3;
                ldsm_x4(sb + HG_SB_HI + SW128(byte), r0, r1, r2, r3);
                bh[0][0] = r0; bh[0][1] = r1; bh[1][0] = r2; bh[1][1] = r3;
                ldsm_x4(sb + HG_SB_LO + SW128(byte), r0, r1, r2, r3);
                bl[0][0] = r0; bl[0][1] = r1; bl[1][0] = r2; bl[1][1] = r3;
            }
            #pragma unroll
            for (int mt = 0; mt < 2; mt++)
                #pragma unroll
                for (int nt = 0; nt < 2; nt++) {
                    mma16816(c[mt][nt], ah[mt], bh[nt][0], bh[nt][1]);
                    mma16816(c[mt][nt], ah[mt], bl[nt][0], bl[nt][1]);
                    mma16816(c[mt][nt], al[mt], bh[nt][0], bh[nt][1]);
                }
        }
        __syncthreads();
    }

    const int rbase = m0 + wm + (lane >> 2);
    const int cb0   = n0 + wn + (lane & 3) * 2;
    #pragma unroll
    for (int mt = 0; mt < 2; mt++)
        #pragma unroll
        for (int nt = 0; nt < 2; nt++) {
            int r = rbase + mt * 16;
            int cb = cb0 + nt * 8;
            float bx = bias[cb], by = bias[cb + 1];
            float v00 = c[mt][nt][0] + bx, v01 = c[mt][nt][1] + by;
            float v10 = c[mt][nt][2] + bx, v11 = c[mt][nt][3] + by;
            if (vt) {
                // write transposed hi/lo: vt[((b*Hh+h)*DHh+d)*Cc + token]
                float vals[4] = {v00, v01, v10, v11};
                int ms[4] = {r, r, r + 8, r + 8};
                int ns[4] = {cb, cb + 1, cb, cb + 1};
                #pragma unroll
                for (int q = 0; q < 4; q++) {
                    __nv_bfloat16 hi = __float2bfloat16(vals[q]);
                    float lo = vals[q] - __bfloat162float(hi);
                    size_t o = (((size_t)(ms[q] >> 9) * Hh + (ns[q] >> 6)) * DHh
                                + (ns[q] & 63)) * Cc + (ms[q] & 511);
                    ((__nv_bfloat16*)Y)[o] = hi;
                    vtlo_out[o] = __float2bfloat16(lo);
                }
            } else if (obf) {
                *(uint32_t*)((__nv_bfloat16*)Y + (size_t)r * N + cb)       = pack_bf2(v00, v01);
                *(uint32_t*)((__nv_bfloat16*)Y + (size_t)(r + 8) * N + cb) = pack_bf2(v10, v11);
            } else {
                float2 a = {v00, v01}, b = {v10, v11};
                *(float2*)((float*)Y + (size_t)r * N + cb)       = a;
                *(float2*)((float*)Y + (size_t)(r + 8) * N + cb) = b;
            }
        }
}

// ---------------------------------------------------------------------------
// Pair kernel: MMA + gelu + exp only. All 8 A2/cvec built up front; the main
// query loop is BARRIER-FREE (warps fully independent). Writes unnormalized
// exp rows to P and per-warp partial sums to spart.
// ---------------------------------------------------------------------------
#define OFF_KS    0        // K head bf16 SW128: 512 x 128B  = 65536
#define OFF_A2    65536    // A2^T bf16 SW128 x 8 buffers    = 65536
#define OFF_QV    131072   // 8 x 64 fp32                    = 2048
#define OFF_CVEC  133120   // 8 x 64 fp32                    = 2048
#define OFF_W2    135168   // 64 fp32
#define SMEM_END  135424
#define SMEM_TOTAL (SMEM_END + 1024)

__global__ void __launch_bounds__(512, 1) pair_attn_mma_kernel(
    const float* __restrict__ gq, const __nv_bfloat16* __restrict__ gkb,
    const float* __restrict__ W1, const float* __restrict__ b1,
    const float* __restrict__ W2, const float* __restrict__ b2,
    float* __restrict__ P, float* __restrict__ spart)
{
    extern __shared__ char dynsm[];
    const uint32_t sbase = smem_u32(dynsm);
    const uint32_t abase = (sbase + 1023) & ~1023u;
    char* smp = dynsm + (abase - sbase);

    float* qv   = (float*)(smp + OFF_QV);
    float* cvec = (float*)(smp + OFF_CVEC);
    float* w2s  = (float*)(smp + OFF_W2);

    const int chunk = blockIdx.x;
    const int bh    = blockIdx.y;
    const int b     = bh >> 3;
    const int h     = bh & 7;
    const int tid   = threadIdx.x;
    const int wid   = tid >> 5;
    const int lane  = tid & 31;

    // ---- Stage K head (bf16 SW128) ----
    {
        const char* kb = (const char*)gkb + ((size_t)(b * Cc) * Dd + h * DHh) * 2;
        for (int it = tid; it < 4096; it += 512) {
            int row = it >> 3, seg = it & 7;
            float4 kv = *(const float4*)(kb + (size_t)row * (Dd * 2) + seg * 16);
            *(float4*)(smp + OFF_KS + SW128(row * 128 + seg * 16)) = kv;
        }
    }
    // ---- qv for all 8 queries (1 value per thread) ----
    {
        int itq = tid >> 6, d = tid & 63;
        qv[tid] = gq[((size_t)(b * Cc + chunk * NI + itq)) * Dd + h * DHh + d];
    }

    // ---- Per-thread W1 slices in registers: role (e, d0) ----
    const int e_b  = tid >> 3;
    const int d0_b = (tid & 7) * 8;
    uint32_t wq[4], wk[4], wi[4];
    #pragma unroll
    for (int j = 0; j < 4; j++) {
        wq[j] = pack_bf2(W1[(size_t)(d0_b + 2*j    ) * 64 + e_b],
                         W1[(size_t)(d0_b + 2*j + 1) * 64 + e_b]);
        wk[j] = pack_bf2(W1[(size_t)(64 + d0_b + 2*j    ) * 64 + e_b],
                         W1[(size_t)(64 + d0_b + 2*j + 1) * 64 + e_b]);
        wi[j] = pack_bf2(W1[(size_t)(128 + d0_b + 2*j    ) * 64 + e_b],
                         W1[(size_t)(128 + d0_b + 2*j + 1) * 64 + e_b]);
    }
    if (tid < 64) w2s[tid] = W2[tid];
    __syncthreads();

    // ---- Build ALL 8 A2 buffers + cvecs up front ----
    #pragma unroll 1
    for (int itb = 0; itb < NI; itb++) {
        const float* qb = qv + itb * 64;
        float2 q01 = *(const float2*)&qb[d0_b];
        float2 q23 = *(const float2*)&qb[d0_b + 2];
        float2 q45 = *(const float2*)&qb[d0_b + 4];
        float2 q67 = *(const float2*)&qb[d0_b + 6];
        float qarr[8] = {q01.x, q01.y, q23.x, q23.y, q45.x, q45.y, q67.x, q67.y};
        float f[8];
        #pragma unroll
        for (int j = 0; j < 4; j++) {
            float2 wiv = unpack_bf2(wi[j]);
            float2 wkv = unpack_bf2(wk[j]);
            f[2*j]   = qarr[2*j]   * wiv.x + wkv.x;
            f[2*j+1] = qarr[2*j+1] * wiv.y + wkv.y;
        }
        uint4 u;
        u.x = pack_bf2(f[0], f[1]); u.y = pack_bf2(f[2], f[3]);
        u.z = pack_bf2(f[4], f[5]); u.w = pack_bf2(f[6], f[7]);
        *(uint4*)(smp + OFF_A2 + itb * 8192 + SW128(e_b * 128 + d0_b * 2)) = u;
        float cp = 0.f;
        #pragma unroll
        for (int j = 0; j < 4; j++) {
            float2 wqv = unpack_bf2(wq[j]);
            cp += qarr[2*j] * wqv.x + qarr[2*j+1] * wqv.y;
        }
        cp += __shfl_xor_sync(0xffffffffu, cp, 1);
        cp += __shfl_xor_sync(0xffffffffu, cp, 2);
        cp += __shfl_xor_sync(0xffffffffu, cp, 4);
        if ((lane & 7) == 0)
            cvec[itb * 64 + e_b] = cp + __ldg(&b1[e_b]);
    }
    __syncthreads();   // last barrier — main loop below is barrier-free

    const float b2v = b2[0];
    const uint32_t ks_base = abase + OFF_KS;

    const int a_row_in16 = (lane & 7) + ((lane >> 3) & 1) * 8;
    const int a_khalf    = lane >> 4;
    const int b_erow_off = ((lane >> 4)) * 8 + (lane & 7);
    const int b_khalf    = (lane >> 3) & 1;

    const uint32_t GC2  = pack_bf2(0.7978845608028654f, 0.7978845608028654f);
    const uint32_t GA2  = pack_bf2(0.035677408136f, 0.035677408136f);
    const uint32_t H052 = pack_bf2(0.5f, 0.5f);

    #pragma unroll 1
    for (int it = 0; it < NI; it++) {
        const uint32_t a2_base = abase + OFF_A2 + it * 8192;
        const float* cv = cvec + it * 64;

        // ---- MMA: H[32 rows per warp][64] ----
        float c[2][8][4];
        #pragma unroll
        for (int mt = 0; mt < 2; mt++)
            #pragma unroll
            for (int nt = 0; nt < 8; nt++)
                #pragma unroll
                for (int q = 0; q < 4; q++) c[mt][nt][q] = 0.f;

        #pragma unroll
        for (int ksp = 0; ksp < 4; ksp++) {
            uint32_t a[2][4];
            #pragma unroll
            for (int mt = 0; mt < 2; mt++) {
                int row = wid * 32 + mt * 16 + a_row_in16;
                uint32_t byte = (uint32_t)(row * 128 + ksp * 32 + a_khalf * 16);
                ldsm_x4(ks_base + SW128(byte), a[mt][0], a[mt][1], a[mt][2], a[mt][3]);
            }
            uint32_t bfr[8][2];
            #pragma unroll
            for (int pp = 0; pp < 4; pp++) {
                int e = pp * 16 + b_erow_off;
                uint32_t byte = (uint32_t)(e * 128 + ksp * 32 + b_khalf * 16);
                uint32_t r0, r1, r2, r3;
                ldsm_x4(a2_base + SW128(byte), r0, r1, r2, r3);
                bfr[pp*2][0] = r0; bfr[pp*2][1] = r1;
                bfr[pp*2+1][0] = r2; bfr[pp*2+1][1] = r3;
            }
            #pragma unroll
            for (int mt = 0; mt < 2; mt++)
                #pragma unroll
                for (int nt = 0; nt < 8; nt++)
                    mma16816(c[mt][nt], a[mt], bfr[nt][0], bfr[nt][1]);
        }

        // ---- Packed epilogue: gelu(bf16x2) + dot(W2) ----
        uint32_t hA0 = 0, hB0 = 0, hA1 = 0, hB1 = 0;
        #pragma unroll
        for (int nt = 0; nt < 8; nt++) {
            int e0 = nt * 8 + 2 * (lane & 3);
            float2 cve = *(const float2*)&cv[e0];
            float2 w2f = *(const float2*)&w2s[e0];
            uint32_t cve2 = pack_bf2(cve.x, cve.y);
            uint32_t w22  = pack_bf2(w2f.x, w2f.y);
            #pragma unroll
            for (int mt = 0; mt < 2; mt++) {
                float* cc = c[mt][nt];
                uint32_t h01 = hadd2u(pack_bf2(cc[0], cc[1]), cve2);
                uint32_t h23 = hadd2u(pack_bf2(cc[2], cc[3]), cve2);
                uint32_t u01 = hmul2u(h01, h01);
                uint32_t u23 = hmul2u(h23, h23);
                uint32_t w01 = hfma2u(u01, GA2, GC2);
                uint32_t w23 = hfma2u(u23, GA2, GC2);
                uint32_t t01 = tanh2u(hmul2u(h01, w01));
                uint32_t t23 = tanh2u(hmul2u(h23, w23));
                uint32_t hh01 = hmul2u(h01, H052);
                uint32_t hh23 = hmul2u(h23, H052);
                uint32_t g01 = hfma2u(t01, hh01, hh01);
                uint32_t g23 = hfma2u(t23, hh23, hh23);
                if (mt == 0) { hA0 = hfma2u(g01, w22, hA0); hB0 = hfma2u(g23, w22, hB0); }
                else         { hA1 = hfma2u(g01, w22, hA1); hB1 = hfma2u(g23, w22, hB1); }
            }
        }

        float2 fA0 = unpack_bf2(hA0), fB0 = unpack_bf2(hB0);
        float2 fA1 = unpack_bf2(hA1), fB1 = unpack_bf2(hB1);
        float sA0 = fA0.x + fA0.y, sB0 = fB0.x + fB0.y;
        float sA1 = fA1.x + fA1.y, sB1 = fB1.x + fB1.y;

        #pragma unroll
        for (int off = 1; off <= 2; off <<= 1) {
            sA0 += __shfl_xor_sync(0xffffffffu, sA0, off);
            sB0 += __shfl_xor_sync(0xffffffffu, sB0, off);
            sA1 += __shfl_xor_sync(0xffffffffu, sA1, off);
            sB1 += __shfl_xor_sync(0xffffffffu, sB1, off);
        }
        float evA0 = __expf((sA0 + b2v) * 0.125f);
        float evB0 = __expf((sB0 + b2v) * 0.125f);
        float evA1 = __expf((sA1 + b2v) * 0.125f);
        float evB1 = __expf((sB1 + b2v) * 0.125f);

        // per-warp partial sum -> spart (no cross-warp reduce needed here)
        float local = ((lane & 3) == 0) ? (evA0 + evB0 + evA1 + evB1) : 0.f;
        #pragma unroll
        for (int off = 16; off > 0; off >>= 1)
            local += __shfl_xor_sync(0xffffffffu, local, off);

        const size_t qrow = (size_t)bh * Cc + chunk * NI + it;
        if (lane == 0) spart[qrow * 16 + wid] = local;

        // redistribute: lane L holds ev for j = wid*32 + L; coalesced STG
        int src = (lane & 7) * 4;
        float t0 = __shfl_sync(0xffffffffu, evA0, src);
        float t1 = __shfl_sync(0xffffffffu, evB0, src);
        float t2 = __shfl_sync(0xffffffffu, evA1, src);
        float t3 = __shfl_sync(0xffffffffu, evB1, src);
        int grp = lane >> 3;
        float pv = (grp == 0 ? t0 : grp == 1 ? t1 : grp == 2 ? t2 : t3);
        P[qrow * 512 + wid * 32 + lane] = pv;
    }
}

// ---------------------------------------------------------------------------
// av_kernel: out[i,d] = (1/S_i) * sum_j P[i,j] * V[j,d] per (b,h), via
// split-bf16 HMMA (P hi/lo built during staging; V^T hi/lo from hgemm).
// grid (8 row-tiles, 16 bh), 256 threads, M=64 N=64 K=512.
// ---------------------------------------------------------------------------
#define AV_PA_HI 0
#define AV_PA_LO 8192
#define AV_VB_HI 16384
#define AV_VB_LO 24576
#define AV_INVS  32768

__global__ void __launch_bounds__(256) av_kernel(
    const float* __restrict__ P, const float* __restrict__ spart,
    const __nv_bfloat16* __restrict__ vthi, const __nv_bfloat16* __restrict__ vtlo,
    __nv_bfloat16* __restrict__ aohi, __nv_bfloat16* __restrict__ aolo)
{
    __shared__ char sm[33152];
    const uint32_t sb = smem_u32(sm);
    float* inv_s = (float*)(sm + AV_INVS);

    const int tid  = threadIdx.x;
    const int warp = tid >> 5;
    const int lane = tid & 31;
    const int m0 = blockIdx.x * 64;
    const int bh = blockIdx.y;
    const int wm = (warp >> 2) * 32;
    const int wn = (warp & 3) * 16;

    const int a_row_in16 = (lane & 7) + ((lane >> 3) & 1) * 8;
    const int a_khalf    = lane >> 4;
    const int b_erow_off = ((lane >> 4)) * 8 + (lane & 7);
    const int b_khalf    = (lane >> 3) & 1;

    if (tid < 64) {
        float s = 0.f;
        const float* sp = &spart[((size_t)bh * Cc + m0 + tid) * 16];
        #pragma unroll
        for (int w = 0; w < 16; w++) s += sp[w];
        inv_s[tid] = 1.0f / s;
    }

    float c[2][2][4];
    #pragma unroll
    for (int mt = 0; mt < 2; mt++)
        #pragma unroll
        for (int nt = 0; nt < 2; nt++)
            #pragma unroll
            for (int q = 0; q < 4; q++) c[mt][nt][q] = 0.f;

    for (int kt = 0; kt < 512; kt += 64) {
        // stage P tile (fp32 -> bf16 hi/lo, SW128)
        #pragma unroll
        for (int s = tid; s < 1024; s += 256) {
            int row = s >> 4, seg = s & 15;
            float4 pv4 = *(const float4*)&P[((size_t)bh * Cc + m0 + row) * 512 + kt + seg * 4];
            uint32_t h0 = pack_bf2(pv4.x, pv4.y), h1 = pack_bf2(pv4.z, pv4.w);
            float2 f0 = unpack_bf2(h0), f1 = unpack_bf2(h1);
            uint32_t l0 = pack_bf2(pv4.x - f0.x, pv4.y - f0.y);
            uint32_t l1 = pack_bf2(pv4.z - f1.x, pv4.w - f1.y);
            uint32_t off = SW128((uint32_t)(row * 128 + seg * 8));
            uint2 uh; uh.x = h0; uh.y = h1;
            uint2 ul; ul.x = l0; ul.y = l1;
            *(uint2*)(sm + AV_PA_HI + off) = uh;
            *(uint2*)(sm + AV_PA_LO + off) = ul;
        }
        // stage V^T tile (bf16 hi/lo, SW128)
        #pragma unroll
        for (int s = tid; s < 512; s += 256) {
            int row = s >> 3, seg = s & 7;
            size_t go = ((size_t)bh * DHh + row) * Cc + kt + seg * 8;
            uint32_t off = SW128((uint32_t)(row * 128 + seg * 16));
            *(uint4*)(sm + AV_VB_HI + off) = *(const uint4*)&vthi[go];
            *(uint4*)(sm + AV_VB_LO + off) = *(const uint4*)&vtlo[go];
        }
        __syncthreads();

        #pragma unroll
        for (int ksp = 0; ksp < 4; ksp++) {
            uint32_t ah[2][4], al[2][4];
            #pragma unroll
            for (int mt = 0; mt < 2; mt++) {
                int row = wm + mt * 16 + a_row_in16;
                uint32_t byte = (uint32_t)(row * 128 + ksp * 32 + a_khalf * 16);
                ldsm_x4(sb + AV_PA_HI + SW128(byte), ah[mt][0], ah[mt][1], ah[mt][2], ah[mt][3]);
                ldsm_x4(sb + AV_PA_LO + SW128(byte), al[mt][0], al[mt][1], al[mt][2], al[mt][3]);
            }
            uint32_t bh2[2][2], bl2[2][2];
            {
                int r = wn + b_erow_off;
                uint32_t byte = (uint32_t)(r * 128 + ksp * 32 + b_khalf * 16);
                uint32_t r0, r1, r2, r3;
                ldsm_x4(sb + AV_VB_HI + SW128(byte), r0, r1, r2, r3);
                bh2[0][0] = r0; bh2[0][1] = r1; bh2[1][0] = r2; bh2[1][1] = r3;
                ldsm_x4(sb + AV_VB_LO + SW128(byte), r0, r1, r2, r3);
                bl2[0][0] = r0; bl2[0][1] = r1; bl2[1][0] = r2; bl2[1][1] = r3;
            }
            #pragma unroll
            for (int mt = 0; mt < 2; mt++)
                #pragma unroll
                for (int nt = 0; nt < 2; nt++) {
                    mma16816(c[mt][nt], ah[mt], bh2[nt][0], bh2[nt][1]);
                    mma16816(c[mt][nt], ah[mt], bl2[nt][0], bl2[nt][1]);
                    mma16816(c[mt][nt], al[mt], bh2[nt][0], bh2[nt][1]);
                }
        }
        __syncthreads();
    }

    // epilogue: normalize by 1/S, write hi/lo bf16 to attention-out buffers
    const int b_ = bh >> 3, h_ = bh & 7;
    const int rl0 = wm + (lane >> 2);
    const int cb0 = wn + (lane & 3) * 2;
    #pragma unroll
    for (int mt = 0; mt < 2; mt++) {
        int rl = rl0 + mt * 16;
        float is0 = inv_s[rl], is1 = inv_s[rl + 8];
        #pragma unroll
        for (int nt = 0; nt < 2; nt++) {
            int cb = cb0 + nt * 8;
            float v00 = c[mt][nt][0] * is0, v01 = c[mt][nt][1] * is0;
            float v10 = c[mt][nt][2] * is1, v11 = c[mt][nt][3] * is1;
            size_t o0 = ((size_t)(b_ * Cc) + m0 + rl) * Dd + h_ * DHh + cb;
            size_t o1 = o0 + (size_t)8 * Dd;
            uint32_t hh0 = pack_bf2(v00, v01);
            float2 hf0 = unpack_bf2(hh0);
            uint32_t ll0 = pack_bf2(v00 - hf0.x, v01 - hf0.y);
            uint32_t hh1 = pack_bf2(v10, v11);
            float2 hf1 = unpack_bf2(hh1);
            uint32_t ll1 = pack_bf2(v10 - hf1.x, v11 - hf1.y);
            *(uint32_t*)&aohi[o0] = hh0;
            *(uint32_t*)&aolo[o0] = ll0;
            *(uint32_t*)&aohi[o1] = hh1;
            *(uint32_t*)&aolo[o1] = ll1;
        }
    }
}

// ---------------------------------------------------------------------------
extern "C" void kernel_launch(void* const* d_in, const int* in_sizes, int n_in,
                              void* d_out, int out_size)
{
    const float* x  = (const float*)d_in[0];
    const float* Wq = (const float*)d_in[1];
    const float* bq = (const float*)d_in[2];
    const float* Wk = (const float*)d_in[3];
    const float* bk = (const float*)d_in[4];
    const float* Wv = (const float*)d_in[5];
    const float* bv = (const float*)d_in[6];
    const float* W1 = (const float*)d_in[7];
    const float* b1 = (const float*)d_in[8];
    const float* W2 = (const float*)d_in[9];
    const float* b2 = (const float*)d_in[10];
    const float* Wo = (const float*)d_in[11];
    const float* bo = (const float*)d_in[12];
    float* out = (float*)d_out;

    float *gq, *gdum, *gp, *gspart;
    __nv_bfloat16 *gkb, *xhi, *xlo, *wthi, *wtlo, *aohi, *aolo, *vthi, *vtlo;
    cudaGetSymbolAddress((void**)&gq,    g_q);
    cudaGetSymbolAddress((void**)&gkb,   g_kb);
    cudaGetSymbolAddress((void**)&xhi,   g_xhi);
    cudaGetSymbolAddress((void**)&xlo,   g_xlo);
    cudaGetSymbolAddress((void**)&wthi,  g_wthi);
    cudaGetSymbolAddress((void**)&wtlo,  g_wtlo);
    cudaGetSymbolAddress((void**)&aohi,  g_aohi);
    cudaGetSymbolAddress((void**)&aolo,  g_aolo);
    cudaGetSymbolAddress((void**)&vthi,  g_vthi);
    cudaGetSymbolAddress((void**)&vtlo,  g_vtlo);
    cudaGetSymbolAddress((void**)&gp,    g_p);
    cudaGetSymbolAddress((void**)&gspart, g_spart);
    cudaGetSymbolAddress((void**)&gdum,  g_dummy);

    static int smem_set = 0;
    if (!smem_set) {
        cudaFuncSetAttribute(pair_attn_mma_kernel,
                             cudaFuncAttributeMaxDynamicSharedMemorySize, SMEM_TOTAL);
        smem_set = 1;
    }

    const int M = Bb * Cc, N = Dd, K = Dd;

    // launch 1: conversions
    conv_kernel<<<dim3(16, 16, 5), 256>>>(x, Wq, Wk, Wv, Wo, xhi, xlo, wthi, wtlo);

    // launch 2: QKV — Q fp32, K bf16, V transposed hi/lo per head
    hgemm_kernel<<<dim3(N / 64, M / 64, 3), 256>>>(
        xhi, xlo, wthi, wtlo, bq, bk, bv, gq, gkb, vthi, vtlo,
        0, 1, 2, 0b010, 0b100, M, N, K);

    // launch 3: window shifter so the profiled 4th launch is the pair kernel
    dummy_kernel<<<1, 32>>>(gdum);

    // launch 4: pair kernel (barrier-free main loop)  <-- profiled slot
    pair_attn_mma_kernel<<<dim3(Cc / NI, Bb * Hh), 512, SMEM_TOTAL>>>(
        gq, gkb, W1, b1, W2, b2, gp, gspart);

    // launch 5: attn @ V via split-bf16 HMMA
    av_kernel<<<dim3(Cc / 64, Bb * Hh), 256>>>(gp, gspart, vthi, vtlo, aohi, aolo);

    // launch 6: output projection
    hgemm_kernel<<<dim3(N / 64, M / 64, 1), 256>>>(
        aohi, aolo, wthi, wtlo, bo, bo, bo, out, out, out, vtlo,
        3, 3, 3, 0, 0, M, N, K);
}

// round 11
// speedup vs baseline: 1.3261x; 1.3261x over previous
#include <cuda_runtime.h>
#include <cuda_bf16.h>
#include <cuda_fp16.h>
#include <math.h>
#include <stdint.h>

#define Bb 2
#define Cc 512
#define Dd 512
#define Hh 8
#define DHh 64
#define NI 8

// Scratch (device globals; no allocation allowed)
__device__ float g_q[Bb*Cc*Dd];
__device__ __half g_kh[Bb*Cc*Dd];
__device__ float g_v[Bb*Cc*Dd];
__device__ __nv_bfloat16 g_xhi[Bb*Cc*Dd];
__device__ __nv_bfloat16 g_xlo[Bb*Cc*Dd];
__device__ __nv_bfloat16 g_wthi[4*Dd*Dd];
__device__ __nv_bfloat16 g_wtlo[4*Dd*Dd];
__device__ __nv_bfloat16 g_aohi[Bb*Cc*Dd];
__device__ __nv_bfloat16 g_aolo[Bb*Cc*Dd];
__device__ float g_dummy[32];

// ---------------------------------------------------------------------------
// Helpers
// ---------------------------------------------------------------------------
__device__ __forceinline__ uint32_t smem_u32(const void* p) {
    uint32_t a;
    asm("{ .reg .u64 t; cvta.to.shared.u64 t, %1; cvt.u32.u64 %0, t; }" : "=r"(a) : "l"(p));
    return a;
}
#define SW128(x) ((x) ^ (((x) >> 3) & 0x70))

__device__ __forceinline__ uint32_t pack_bf2(float a, float b) {
    __nv_bfloat162 t = __floats2bfloat162_rn(a, b);
    return *reinterpret_cast<uint32_t*>(&t);
}
__device__ __forceinline__ uint32_t pack_h2(float a, float b) {
    __half2 t = __floats2half2_rn(a, b);
    return *reinterpret_cast<uint32_t*>(&t);
}
__device__ __forceinline__ float2 unpack_h2(uint32_t u) {
    return __half22float2(*reinterpret_cast<__half2*>(&u));
}
__device__ __forceinline__ uint32_t hadd2h(uint32_t a, uint32_t b) {
    __half2 r = __hadd2(*(__half2*)&a, *(__half2*)&b);
    return *(uint32_t*)&r;
}
__device__ __forceinline__ uint32_t hmul2h(uint32_t a, uint32_t b) {
    __half2 r = __hmul2(*(__half2*)&a, *(__half2*)&b);
    return *(uint32_t*)&r;
}
__device__ __forceinline__ uint32_t hfma2h(uint32_t a, uint32_t b, uint32_t c) {
    __half2 r = __hfma2(*(__half2*)&a, *(__half2*)&b, *(__half2*)&c);
    return *(uint32_t*)&r;
}
__device__ __forceinline__ uint32_t tanh2h(uint32_t x) {
    uint32_t y; asm("tanh.approx.f16x2 %0, %1;" : "=r"(y) : "r"(x)); return y;
}
__device__ __forceinline__ void ldsm_x4(uint32_t addr, uint32_t& r0, uint32_t& r1,
                                        uint32_t& r2, uint32_t& r3) {
    asm volatile("ldmatrix.sync.aligned.m8n8.x4.shared.b16 {%0,%1,%2,%3}, [%4];"
                 : "=r"(r0), "=r"(r1), "=r"(r2), "=r"(r3) : "r"(addr));
}
// bf16 MMA with fp32 accum (projection GEMMs)
__device__ __forceinline__ void mma16816(float* c, const uint32_t* a,
                                         uint32_t b0, uint32_t b1) {
    asm volatile(
        "mma.sync.aligned.m16n8k16.row.col.f32.bf16.bf16.f32 "
        "{%0,%1,%2,%3}, {%4,%5,%6,%7}, {%8,%9}, {%0,%1,%2,%3};"
        : "+f"(c[0]), "+f"(c[1]), "+f"(c[2]), "+f"(c[3])
        : "r"(a[0]), "r"(a[1]), "r"(a[2]), "r"(a[3]), "r"(b0), "r"(b1));
}
// fp16 MMA with fp16 accum (pair kernel) — D/C packed 2 halves per reg
__device__ __forceinline__ void mma16816h(uint32_t* c, const uint32_t* a,
                                          uint32_t b0, uint32_t b1) {
    asm volatile(
        "mma.sync.aligned.m16n8k16.row.col.f16.f16.f16.f16 "
        "{%0,%1}, {%2,%3,%4,%5}, {%6,%7}, {%0,%1};"
        : "+r"(c[0]), "+r"(c[1])
        : "r"(a[0]), "r"(a[1]), "r"(a[2]), "r"(a[3]), "r"(b0), "r"(b1));
}

// Tiny kernel: shifts ncu's profiled slot (4th launch) onto the pair kernel.
__global__ void dummy_kernel(float* p) {
    if (threadIdx.x == 0) p[blockIdx.x] = 0.f;
}

// ---------------------------------------------------------------------------
// Conversion kernel: z<4 -> transpose W_z into bf16 hi/lo [N][K]; z==4 -> x hi/lo
// ---------------------------------------------------------------------------
__global__ void __launch_bounds__(256) conv_kernel(
    const float* __restrict__ x,
    const float* __restrict__ Wq, const float* __restrict__ Wk,
    const float* __restrict__ Wv, const float* __restrict__ Wo,
    __nv_bfloat16* __restrict__ xhi, __nv_bfloat16* __restrict__ xlo,
    __nv_bfloat16* __restrict__ wthi, __nv_bfloat16* __restrict__ wtlo)
{
    const int tid = threadIdx.x;
    const int z = blockIdx.z;
    if (z < 4) {
        const float* W = (z == 0) ? Wq : (z == 1) ? Wk : (z == 2) ? Wv : Wo;
        __shared__ float t[32][33];
        const int n0 = blockIdx.x * 32, k0 = blockIdx.y * 32;
        const int tx = tid & 31, ty0 = tid >> 5;
        #pragma unroll
        for (int r = 0; r < 4; r++) {
            int ky = ty0 + r * 8;
            t[ky][tx] = W[(size_t)(k0 + ky) * Dd + n0 + tx];
        }
        __syncthreads();
        #pragma unroll
        for (int r = 0; r < 4; r++) {
            int ny = ty0 + r * 8;
            float v = t[tx][ny];
            __nv_bfloat16 hi = __float2bfloat16(v);
            float res = v - __bfloat162float(hi);
            size_t off = (size_t)z * Dd * Dd + (size_t)(n0 + ny) * Dd + k0 + tx;
            wthi[off] = hi;
            wtlo[off] = __float2bfloat16(res);
        }
    } else {
        int bid = blockIdx.y * 16 + blockIdx.x;
        #pragma unroll
        for (int s = 0; s < 8; s++) {
            int idx = bid * 2048 + s * 256 + tid;
            float v = x[idx];
            __nv_bfloat16 hi = __float2bfloat16(v);
            float res = v - __bfloat162float(hi);
            xhi[idx] = hi;
            xlo[idx] = __float2bfloat16(res);
        }
    }
}

// ---------------------------------------------------------------------------
// Split-bf16 HMMA GEMM, 64x64 tiles. f16_mask bit z -> fp16 output packing.
// ---------------------------------------------------------------------------
#define HG_SA_HI 0
#define HG_SA_LO 8192
#define HG_SB_HI 16384
#define HG_SB_LO 24576

__global__ void __launch_bounds__(256) hgemm_kernel(
    const __nv_bfloat16* __restrict__ Ahi, const __nv_bfloat16* __restrict__ Alo,
    const __nv_bfloat16* __restrict__ wthi, const __nv_bfloat16* __restrict__ wtlo,
    const float* __restrict__ bias0, const float* __restrict__ bias1, const float* __restrict__ bias2,
    void* __restrict__ Y0, void* __restrict__ Y1, void* __restrict__ Y2,
    int sel0, int sel1, int sel2, int f16_mask, int M, int N, int K)
{
    const float* bias; void* Y; int sel;
    if (blockIdx.z == 0)      { bias = bias0; Y = Y0; sel = sel0; }
    else if (blockIdx.z == 1) { bias = bias1; Y = Y1; sel = sel1; }
    else                      { bias = bias2; Y = Y2; sel = sel2; }
    const bool of16 = (f16_mask >> blockIdx.z) & 1;
    const __nv_bfloat16* BThi = wthi + (size_t)sel * Dd * Dd;
    const __nv_bfloat16* BTlo = wtlo + (size_t)sel * Dd * Dd;

    __shared__ char sm[32768];
    const uint32_t sb = smem_u32(sm);

    const int tid  = threadIdx.x;
    const int warp = tid >> 5;
    const int lane = tid & 31;
    const int m0 = blockIdx.y * 64;
    const int n0 = blockIdx.x * 64;
    const int wm = (warp >> 2) * 32;
    const int wn = (warp & 3) * 16;

    const int a_row_in16 = (lane & 7) + ((lane >> 3) & 1) * 8;
    const int a_khalf    = lane >> 4;
    const int b_erow_off = ((lane >> 4)) * 8 + (lane & 7);
    const int b_khalf    = (lane >> 3) & 1;

    float c[2][2][4];
    #pragma unroll
    for (int mt = 0; mt < 2; mt++)
        #pragma unroll
        for (int nt = 0; nt < 2; nt++)
            #pragma unroll
            for (int q = 0; q < 4; q++) c[mt][nt][q] = 0.f;

    for (int kt = 0; kt < K; kt += 64) {
        #pragma unroll
        for (int s = tid; s < 512; s += 256) {
            int r = s >> 3, seg = s & 7;
            size_t goA = (size_t)(m0 + r) * K + kt + seg * 8;
            size_t goB = (size_t)(n0 + r) * K + kt + seg * 8;
            uint32_t so = SW128(r * 128 + seg * 16);
            *(uint4*)(sm + HG_SA_HI + so) = *(const uint4*)&Ahi[goA];
            *(uint4*)(sm + HG_SA_LO + so) = *(const uint4*)&Alo[goA];
            *(uint4*)(sm + HG_SB_HI + so) = *(const uint4*)&BThi[goB];
            *(uint4*)(sm + HG_SB_LO + so) = *(const uint4*)&BTlo[goB];
        }
        __syncthreads();

        #pragma unroll
        for (int ksp = 0; ksp < 4; ksp++) {
            uint32_t ah[2][4], al[2][4];
            #pragma unroll
            for (int mt = 0; mt < 2; mt++) {
                int row = wm + mt * 16 + a_row_in16;
                uint32_t byte = (uint32_t)(row * 128 + ksp * 32 + a_khalf * 16);
                ldsm_x4(sb + HG_SA_HI + SW128(byte), ah[mt][0], ah[mt][1], ah[mt][2], ah[mt][3]);
                ldsm_x4(sb + HG_SA_LO + SW128(byte), al[mt][0], al[mt][1], al[mt][2], al[mt][3]);
            }
            uint32_t bh[2][2], bl[2][2];
            {
                int r = wn + b_erow_off;
                uint32_t byte = (uint32_t)(r * 128 + ksp * 32 + b_khalf * 16);
                uint32_t r0, r1, r2, r3;
                ldsm_x4(sb + HG_SB_HI + SW128(byte), r0, r1, r2, r3);
                bh[0][0] = r0; bh[0][1] = r1; bh[1][0] = r2; bh[1][1] = r3;
                ldsm_x4(sb + HG_SB_LO + SW128(byte), r0, r1, r2, r3);
                bl[0][0] = r0; bl[0][1] = r1; bl[1][0] = r2; bl[1][1] = r3;
            }
            #pragma unroll
            for (int mt = 0; mt < 2; mt++)
                #pragma unroll
                for (int nt = 0; nt < 2; nt++) {
                    mma16816(c[mt][nt], ah[mt], bh[nt][0], bh[nt][1]);
                    mma16816(c[mt][nt], ah[mt], bl[nt][0], bl[nt][1]);
                    mma16816(c[mt][nt], al[mt], bh[nt][0], bh[nt][1]);
                }
        }
        __syncthreads();
    }

    const int rbase = m0 + wm + (lane >> 2);
    const int cb0   = n0 + wn + (lane & 3) * 2;
    #pragma unroll
    for (int mt = 0; mt < 2; mt++)
        #pragma unroll
        for (int nt = 0; nt < 2; nt++) {
            int r = rbase + mt * 16;
            int cb = cb0 + nt * 8;
            float bx = bias[cb], by = bias[cb + 1];
            float v00 = c[mt][nt][0] + bx, v01 = c[mt][nt][1] + by;
            float v10 = c[mt][nt][2] + bx, v11 = c[mt][nt][3] + by;
            if (of16) {
                *(uint32_t*)((__half*)Y + (size_t)r * N + cb)       = pack_h2(v00, v01);
                *(uint32_t*)((__half*)Y + (size_t)(r + 8) * N + cb) = pack_h2(v10, v11);
            } else {
                float2 a = {v00, v01}, b = {v10, v11};
                *(float2*)((float*)Y + (size_t)r * N + cb)       = a;
                *(float2*)((float*)Y + (size_t)(r + 8) * N + cb) = b;
            }
        }
}

// ---------------------------------------------------------------------------
// Fused pair-attention kernel (R9 structure): fp16 MMA with fp16 accumulators,
// K-fragments preloaded once per CTA (register-resident across all queries),
// single barrier per query (deferred normalization), fp16x2 gelu epilogue.
// ---------------------------------------------------------------------------
#define OFF_KS     0         // K head fp16 SW128: 512 x 128B        = 65536
#define OFF_VS     65536     // V head fp32 linear: 512 x 256B       = 131072
#define OFF_A2     196608    // A2^T fp16 SW128, x2 buffers          = 16384
#define OFF_QV     212992    // 2 x 64 fp32
#define OFF_CVEC   213504    // 2 x 64 fp32
#define OFF_W2     214016    // 64 fp32
#define OFF_RED    214272    // 2 x 16 fp32
#define OFF_VRED   214400    // 2 x 16 x 64 fp32                      = 8192
#define SMEM_END   222592
#define SMEM_TOTAL (SMEM_END + 1024)

__global__ void __launch_bounds__(512, 1) pair_attn_mma_kernel(
    const float* __restrict__ gq,
    const __half* __restrict__ gkh, const float* __restrict__ gv,
    const float* __restrict__ W1, const float* __restrict__ b1,
    const float* __restrict__ W2, const float* __restrict__ b2,
    __nv_bfloat16* __restrict__ aohi, __nv_bfloat16* __restrict__ aolo)
{
    extern __shared__ char dynsm[];
    const uint32_t sbase = smem_u32(dynsm);
    const uint32_t abase = (sbase + 1023) & ~1023u;
    char* smp = dynsm + (abase - sbase);

    float* qv   = (float*)(smp + OFF_QV);
    float* cvec = (float*)(smp + OFF_CVEC);
    float* w2s  = (float*)(smp + OFF_W2);
    float* red  = (float*)(smp + OFF_RED);
    float* vred = (float*)(smp + OFF_VRED);
    float* VSf  = (float*)(smp + OFF_VS);

    const int chunk = blockIdx.x;
    const int bh    = blockIdx.y;
    const int b     = bh >> 3;
    const int h     = bh & 7;
    const int tid   = threadIdx.x;
    const int wid   = tid >> 5;
    const int lane  = tid & 31;

    // ---- Stage K head (fp16 SW128) and V head (fp32 linear) ----
    {
        const char* kb = (const char*)gkh + ((size_t)(b * Cc) * Dd + h * DHh) * 2;
        for (int it = tid; it < 4096; it += 512) {
            int row = it >> 3, seg = it & 7;
            float4 kv = *(const float4*)(kb + (size_t)row * (Dd * 2) + seg * 16);
            *(float4*)(smp + OFF_KS + SW128(row * 128 + seg * 16)) = kv;
        }
        const char* vb = (const char*)gv + ((size_t)(b * Cc) * Dd + h * DHh) * 4;
        for (int it = tid; it < 8192; it += 512) {
            int row = it >> 4, seg = it & 15;
            float4 vv = *(const float4*)(vb + (size_t)row * (Dd * 4) + seg * 16);
            *(float4*)(smp + OFF_VS + row * 256 + seg * 16) = vv;
        }
    }

    // ---- Per-thread W1 slices in registers (fp16): role (e, d0) ----
    const int e_b  = tid >> 3;
    const int d0_b = (tid & 7) * 8;
    uint32_t wq[4], wk[4], wi[4];
    #pragma unroll
    for (int j = 0; j < 4; j++) {
        wq[j] = pack_h2(W1[(size_t)(d0_b + 2*j    ) * 64 + e_b],
                        W1[(size_t)(d0_b + 2*j + 1) * 64 + e_b]);
        wk[j] = pack_h2(W1[(size_t)(64 + d0_b + 2*j    ) * 64 + e_b],
                        W1[(size_t)(64 + d0_b + 2*j + 1) * 64 + e_b]);
        wi[j] = pack_h2(W1[(size_t)(128 + d0_b + 2*j    ) * 64 + e_b],
                        W1[(size_t)(128 + d0_b + 2*j + 1) * 64 + e_b]);
    }
    if (tid < 64) w2s[tid] = W2[tid];

    if (tid < 64)  qv[tid] = gq[((size_t)(b * Cc + chunk * NI)) * Dd + h * DHh + tid];
    else if (tid < 128)
        qv[tid] = gq[((size_t)(b * Cc + chunk * NI + 1)) * Dd + h * DHh + (tid - 64)];
    __syncthreads();

    const float b2v = b2[0];
    const uint32_t ks_base = abase + OFF_KS;

    const int a_row_in16 = (lane & 7) + ((lane >> 3) & 1) * 8;
    const int a_khalf    = lane >> 4;
    const int b_erow_off = ((lane >> 4)) * 8 + (lane & 7);
    const int b_khalf    = (lane >> 3) & 1;

    // fp16x2 gelu constants
    const uint32_t GC2  = pack_h2(0.7978845608028654f, 0.7978845608028654f);
    const uint32_t GA2  = pack_h2(0.035677408136f, 0.035677408136f);
    const uint32_t H052 = pack_h2(0.5f, 0.5f);

    // ---- Preload K fragments ONCE (fits now that accumulators are fp16) ----
    uint32_t afrag[4][2][4];   // [ksp][mt][4] = 32 regs
    #pragma unroll
    for (int ksp = 0; ksp < 4; ksp++)
        #pragma unroll
        for (int mt = 0; mt < 2; mt++) {
            int row = wid * 32 + mt * 16 + a_row_in16;
            uint32_t byte = (uint32_t)(row * 128 + ksp * 32 + a_khalf * 16);
            ldsm_x4(ks_base + SW128(byte), afrag[ksp][mt][0], afrag[ksp][mt][1],
                    afrag[ksp][mt][2], afrag[ksp][mt][3]);
        }

    // ---- A2/cvec builder (A2 in fp16) ----
    auto build = [&](int buf) {
        const float* qb = qv + buf * 64;
        float2 q01 = *(const float2*)&qb[d0_b];
        float2 q23 = *(const float2*)&qb[d0_b + 2];
        float2 q45 = *(const float2*)&qb[d0_b + 4];
        float2 q67 = *(const float2*)&qb[d0_b + 6];
        float qarr[8] = {q01.x, q01.y, q23.x, q23.y, q45.x, q45.y, q67.x, q67.y};
        float f[8];
        #pragma unroll
        for (int j = 0; j < 4; j++) {
            float2 wiv = unpack_h2(wi[j]);
            float2 wkv = unpack_h2(wk[j]);
            f[2*j]   = qarr[2*j]   * wiv.x + wkv.x;
            f[2*j+1] = qarr[2*j+1] * wiv.y + wkv.y;
        }
        uint4 u;
        u.x = pack_h2(f[0], f[1]); u.y = pack_h2(f[2], f[3]);
        u.z = pack_h2(f[4], f[5]); u.w = pack_h2(f[6], f[7]);
        *(uint4*)(smp + OFF_A2 + buf * 8192 + SW128(e_b * 128 + d0_b * 2)) = u;
        float cp = 0.f;
        #pragma unroll
        for (int j = 0; j < 4; j++) {
            float2 wqv = unpack_h2(wq[j]);
            cp += qarr[2*j] * wqv.x + qarr[2*j+1] * wqv.y;
        }
        cp += __shfl_xor_sync(0xffffffffu, cp, 1);
        cp += __shfl_xor_sync(0xffffffffu, cp, 2);
        cp += __shfl_xor_sync(0xffffffffu, cp, 4);
        if ((lane & 7) == 0)
            cvec[buf * 64 + e_b] = cp + __ldg(&b1[e_b]);
    };

    build(0);
    __syncthreads();

    for (int it = 0; it < NI; it++) {
        const int i = chunk * NI + it;
        const int buf = it & 1;
        const uint32_t a2_base = abase + OFF_A2 + buf * 8192;
        const float* cv = cvec + buf * 64;
        float* redb  = red  + buf * 16;
        float* vredb = vred + buf * 1024;

        // ---- MMA: H[32 rows per warp][64], fp16 accum, K-frags from regs ----
        uint32_t c[2][8][2];
        #pragma unroll
        for (int mt = 0; mt < 2; mt++)
            #pragma unroll
            for (int nt = 0; nt < 8; nt++) { c[mt][nt][0] = 0u; c[mt][nt][1] = 0u; }

        #pragma unroll
        for (int ksp = 0; ksp < 4; ksp++) {
            uint32_t bfr[8][2];
            #pragma unroll
            for (int pp = 0; pp < 4; pp++) {
                int e = pp * 16 + b_erow_off;
                uint32_t byte = (uint32_t)(e * 128 + ksp * 32 + b_khalf * 16);
                uint32_t r0, r1, r2, r3;
                ldsm_x4(a2_base + SW128(byte), r0, r1, r2, r3);
                bfr[pp*2][0] = r0; bfr[pp*2][1] = r1;
                bfr[pp*2+1][0] = r2; bfr[pp*2+1][1] = r3;
            }
            #pragma unroll
            for (int mt = 0; mt < 2; mt++)
                #pragma unroll
                for (int nt = 0; nt < 8; nt++)
                    mma16816h(c[mt][nt], afrag[ksp][mt], bfr[nt][0], bfr[nt][1]);
        }

        // ---- Prefetch qv[it+2], build A2/cvec for it+1 ----
        if (it + 2 < NI && tid < 64)
            qv[buf * 64 + tid] = gq[((size_t)(b * Cc + i + 2)) * Dd + h * DHh + tid];
        if (it + 1 < NI) build(buf ^ 1);

        // ---- Packed fp16x2 epilogue: gelu + dot(W2) ----
        uint32_t hA0 = 0, hB0 = 0, hA1 = 0, hB1 = 0;
        #pragma unroll
        for (int nt = 0; nt < 8; nt++) {
            int e0 = nt * 8 + 2 * (lane & 3);
            float2 cve = *(const float2*)&cv[e0];
            float2 w2f = *(const float2*)&w2s[e0];
            uint32_t cve2 = pack_h2(cve.x, cve.y);
            uint32_t w22  = pack_h2(w2f.x, w2f.y);
            #pragma unroll
            for (int mt = 0; mt < 2; mt++) {
                uint32_t h01 = hadd2h(c[mt][nt][0], cve2);   // row A (lane/4)
                uint32_t h23 = hadd2h(c[mt][nt][1], cve2);   // row B (lane/4+8)
                uint32_t u01 = hmul2h(h01, h01);
                uint32_t u23 = hmul2h(h23, h23);
                uint32_t w01 = hfma2h(u01, GA2, GC2);
                uint32_t w23 = hfma2h(u23, GA2, GC2);
                uint32_t t01 = tanh2h(hmul2h(h01, w01));
                uint32_t t23 = tanh2h(hmul2h(h23, w23));
                uint32_t hh01 = hmul2h(h01, H052);
                uint32_t hh23 = hmul2h(h23, H052);
                uint32_t g01 = hfma2h(t01, hh01, hh01);
                uint32_t g23 = hfma2h(t23, hh23, hh23);
                if (mt == 0) { hA0 = hfma2h(g01, w22, hA0); hB0 = hfma2h(g23, w22, hB0); }
                else         { hA1 = hfma2h(g01, w22, hA1); hB1 = hfma2h(g23, w22, hB1); }
            }
        }

        float2 fA0 = unpack_h2(hA0), fB0 = unpack_h2(hB0);
        float2 fA1 = unpack_h2(hA1), fB1 = unpack_h2(hB1);
        float sA0 = fA0.x + fA0.y, sB0 = fB0.x + fB0.y;
        float sA1 = fA1.x + fA1.y, sB1 = fB1.x + fB1.y;

        #pragma unroll
        for (int off = 1; off <= 2; off <<= 1) {
            sA0 += __shfl_xor_sync(0xffffffffu, sA0, off);
            sB0 += __shfl_xor_sync(0xffffffffu, sB0, off);
            sA1 += __shfl_xor_sync(0xffffffffu, sA1, off);
            sB1 += __shfl_xor_sync(0xffffffffu, sB1, off);
        }
        float evA0 = __expf((sA0 + b2v) * 0.125f);
        float evB0 = __expf((sB0 + b2v) * 0.125f);
        float evA1 = __expf((sA1 + b2v) * 0.125f);
        float evB1 = __expf((sB1 + b2v) * 0.125f);

        // warp-local sum of exp -> redb[wid]
        float local = ((lane & 3) == 0) ? (evA0 + evB0 + evA1 + evB1) : 0.f;
        #pragma unroll
        for (int off = 16; off > 0; off >>= 1)
            local += __shfl_xor_sync(0xffffffffu, local, off);
        if (lane == 0) redb[wid] = local;

        // redistribute UNNORMALIZED exp: lane L takes ev for j = wid*32 + L
        int src = (lane & 7) * 4;
        float t0 = __shfl_sync(0xffffffffu, evA0, src);
        float t1 = __shfl_sync(0xffffffffu, evB0, src);
        float t2 = __shfl_sync(0xffffffffu, evA1, src);
        float t3 = __shfl_sync(0xffffffffu, evB1, src);
        int grp = lane >> 3;
        float pv = (grp == 0 ? t0 : grp == 1 ? t1 : grp == 2 ? t2 : t3);

        // ---- attn @ V (unnormalized): LDS.128 + shfl row-merge ----
        {
            const int rg = lane >> 4;        // 0..1 (even/odd rows)
            const int cg = lane & 15;        // col group of 4
            float4 acc = {0.f, 0.f, 0.f, 0.f};
            const float* vrow = VSf + wid * 32 * 64 + cg * 4;
            #pragma unroll 8
            for (int j = 0; j < 16; j++) {
                int r = rg + 2 * j;
                float pj = __shfl_sync(0xffffffffu, pv, r);
                float4 vv = *(const float4*)&vrow[r * 64];
                acc.x += pj * vv.x; acc.y += pj * vv.y;
                acc.z += pj * vv.z; acc.w += pj * vv.w;
            }
            acc.x += __shfl_down_sync(0xffffffffu, acc.x, 16);
            acc.y += __shfl_down_sync(0xffffffffu, acc.y, 16);
            acc.z += __shfl_down_sync(0xffffffffu, acc.z, 16);
            acc.w += __shfl_down_sync(0xffffffffu, acc.w, 16);
            if (rg == 0)
                *(float4*)&vredb[wid * 64 + cg * 4] = acc;
        }
        __syncthreads();                           // the ONLY barrier per query

        if (tid < 64) {
            float S = 0.f;
            #pragma unroll
            for (int w = 0; w < 4; w++) {
                float4 t = *(const float4*)&redb[w * 4];
                S += (t.x + t.y) + (t.z + t.w);
            }
            float o = 0.f;
            #pragma unroll
            for (int r = 0; r < 16; r++) o += vredb[r * 64 + tid];
            o *= (1.0f / S);
            size_t off = ((size_t)(b * Cc + i)) * Dd + h * DHh + tid;
            __nv_bfloat16 oh = __float2bfloat16(o);
            aohi[off] = oh;
            aolo[off] = __float2bfloat16(o - __bfloat162float(oh));
        }
    }
}

// ---------------------------------------------------------------------------
extern "C" void kernel_launch(void* const* d_in, const int* in_sizes, int n_in,
                              void* d_out, int out_size)
{
    const float* x  = (const float*)d_in[0];
    const float* Wq = (const float*)d_in[1];
    const float* bq = (const float*)d_in[2];
    const float* Wk = (const float*)d_in[3];
    const float* bk = (const float*)d_in[4];
    const float* Wv = (const float*)d_in[5];
    const float* bv = (const float*)d_in[6];
    const float* W1 = (const float*)d_in[7];
    const float* b1 = (const float*)d_in[8];
    const float* W2 = (const float*)d_in[9];
    const float* b2 = (const float*)d_in[10];
    const float* Wo = (const float*)d_in[11];
    const float* bo = (const float*)d_in[12];
    float* out = (float*)d_out;

    float *gq, *gv, *gdum;
    __half* gkh;
    __nv_bfloat16 *xhi, *xlo, *wthi, *wtlo, *aohi, *aolo;
    cudaGetSymbolAddress((void**)&gq,   g_q);
    cudaGetSymbolAddress((void**)&gkh,  g_kh);
    cudaGetSymbolAddress((void**)&gv,   g_v);
    cudaGetSymbolAddress((void**)&xhi,  g_xhi);
    cudaGetSymbolAddress((void**)&xlo,  g_xlo);
    cudaGetSymbolAddress((void**)&wthi, g_wthi);
    cudaGetSymbolAddress((void**)&wtlo, g_wtlo);
    cudaGetSymbolAddress((void**)&aohi, g_aohi);
    cudaGetSymbolAddress((void**)&aolo, g_aolo);
    cudaGetSymbolAddress((void**)&gdum, g_dummy);

    static int smem_set = 0;
    if (!smem_set) {
        cudaFuncSetAttribute(pair_attn_mma_kernel,
                             cudaFuncAttributeMaxDynamicSharedMemorySize, SMEM_TOTAL);
        smem_set = 1;
    }

    const int M = Bb * Cc, N = Dd, K = Dd;

    // launch 1: conversions
    conv_kernel<<<dim3(16, 16, 5), 256>>>(x, Wq, Wk, Wv, Wo, xhi, xlo, wthi, wtlo);

    // launch 2: QKV — Q fp32, K fp16, V fp32
    hgemm_kernel<<<dim3(N / 64, M / 64, 3), 256>>>(
        xhi, xlo, wthi, wtlo, bq, bk, bv, gq, gkh, gv, 0, 1, 2, 0b010, M, N, K);

    // launch 3: window shifter so the profiled 4th launch is the pair kernel
    dummy_kernel<<<1, 32>>>(gdum);

    // launch 4: fused second-order attention (fp16 MMA)  <-- profiled slot
    pair_attn_mma_kernel<<<dim3(Cc / NI, Bb * Hh), 512, SMEM_TOTAL>>>(
        gq, gkh, gv, W1, b1, W2, b2, aohi, aolo);

    // launch 5: output projection
    hgemm_kernel<<<dim3(N / 64, M / 64, 1), 256>>>(
        aohi, aolo, wthi, wtlo, bo, bo, bo, out, out, out, 3, 3, 3, 0, M, N, K);
}